// round 17
// baseline (speedup 1.0000x reference)
#include <cuda_runtime.h>
#include <cuda_fp16.h>
#include <stdint.h>
#include <math.h>

#define MTOT 16384
#define CDIM 512
#define NQKV 1536
#define LOG2E 1.44269504088896f

// ---------------------------------------------------------------------------
// Scratch (static __device__: no allocations allowed)
// ---------------------------------------------------------------------------
__device__ __half g_x16[MTOT * CDIM];
__device__ __half g_qkv16[(size_t)MTOT * NQKV];
__device__ __half g_s16[MTOT * CDIM];       // scramble-layout attn output
__device__ __half g_w16[4 * CDIM * CDIM];   // Wq, Wk, Wv, proj

// ---------------------------------------------------------------------------
// PTX helpers (arch-portable)
// ---------------------------------------------------------------------------
__device__ __forceinline__ uint32_t smem_u32(const void* p) {
    uint32_t a;
    asm("{ .reg .u64 t; cvta.to.shared.u64 t, %1; cvt.u32.u64 %0, t; }"
        : "=r"(a) : "l"(p));
    return a;
}
__device__ __forceinline__ void ldm_x4(uint32_t* r, uint32_t addr) {
    asm volatile("ldmatrix.sync.aligned.m8n8.x4.shared.b16 {%0,%1,%2,%3}, [%4];"
                 : "=r"(r[0]), "=r"(r[1]), "=r"(r[2]), "=r"(r[3]) : "r"(addr));
}
__device__ __forceinline__ void ldm_x2(uint32_t* r, uint32_t addr) {
    asm volatile("ldmatrix.sync.aligned.m8n8.x2.shared.b16 {%0,%1}, [%2];"
                 : "=r"(r[0]), "=r"(r[1]) : "r"(addr));
}
__device__ __forceinline__ void ldm_x4_trans(uint32_t* r, uint32_t addr) {
    asm volatile("ldmatrix.sync.aligned.m8n8.x4.trans.shared.b16 {%0,%1,%2,%3}, [%4];"
                 : "=r"(r[0]), "=r"(r[1]), "=r"(r[2]), "=r"(r[3]) : "r"(addr));
}
__device__ __forceinline__ void mma_f16(float* d, const uint32_t* a, const uint32_t* b) {
    asm volatile(
        "mma.sync.aligned.m16n8k16.row.col.f32.f16.f16.f32 "
        "{%0,%1,%2,%3}, {%4,%5,%6,%7}, {%8,%9}, {%0,%1,%2,%3};"
        : "+f"(d[0]), "+f"(d[1]), "+f"(d[2]), "+f"(d[3])
        : "r"(a[0]), "r"(a[1]), "r"(a[2]), "r"(a[3]), "r"(b[0]), "r"(b[1]));
}
__device__ __forceinline__ void mma_f16_k8(float* d, uint32_t a0, uint32_t a1, uint32_t b0) {
    asm volatile(
        "mma.sync.aligned.m16n8k8.row.col.f32.f16.f16.f32 "
        "{%0,%1,%2,%3}, {%4,%5}, {%6}, {%0,%1,%2,%3};"
        : "+f"(d[0]), "+f"(d[1]), "+f"(d[2]), "+f"(d[3])
        : "r"(a0), "r"(a1), "r"(b0));
}
__device__ __forceinline__ void cp_async16(uint32_t dst, const void* src) {
    asm volatile("cp.async.cg.shared.global [%0], [%1], 16;" :: "r"(dst), "l"(src));
}
#define CP_COMMIT() asm volatile("cp.async.commit_group;" ::: "memory")
#define CP_WAIT(N)  asm volatile("cp.async.wait_group %0;" :: "n"(N) : "memory")

__device__ __forceinline__ uint32_t pack_h2(float a, float b) {
    __half2 h = __floats2half2_rn(a, b);
    return *(uint32_t*)&h;
}
__device__ __forceinline__ float ex2f(float x) {
    float r;
    asm("ex2.approx.f32 %0, %1;" : "=f"(r) : "f"(x));
    return r;
}

// ---------------------------------------------------------------------------
// fp16 GEMM (R16, unchanged): BM=128, BN=128, BK=64, 256 threads, 3-stage,
// 2 CTAs/SM, single barrier per mainloop iteration. Pitch 72.
// ---------------------------------------------------------------------------
#define PITCH 72
#define SH (256 * PITCH)
#define OFF_B (128 * PITCH)
#define GSMEM (3 * SH * 2)                 // 110592 B

template <bool HOUT>
__global__ __launch_bounds__(256, 2)
void gemm_f16(const __half* __restrict__ A, const __half* __restrict__ B,
              const float* __restrict__ bias, void* __restrict__ Cv, int ldc)
{
    extern __shared__ __align__(16) __half sm[];
    const int tid = threadIdx.x;
    const int wid = tid >> 5, L = tid & 31;
    const int m0 = blockIdx.y * 128;
    const int n0 = blockIdx.x * 128;
    const int wm = (wid >> 2) * 64;
    const int wn = (wid & 3) * 32;
    const uint32_t sb = smem_u32(sm);

    const __half* Ab = A + (size_t)m0 * CDIM;
    const __half* Bb = B + (size_t)n0 * CDIM;

    float acc[4][4][4];
#pragma unroll
    for (int i = 0; i < 4; i++)
#pragma unroll
        for (int j = 0; j < 4; j++)
#pragma unroll
            for (int q = 0; q < 4; q++) acc[i][j][q] = 0.f;

    const int aRow = L & 15, aK = (L >> 4) * 8;
    const int bRowL = (L & 7) + ((L & 16) ? 8 : 0);
    const int bK = ((L >> 3) & 1) * 8;

    auto load_stage = [&](int stage, int k0) {
        const uint32_t s0 = sb + (uint32_t)stage * SH * 2;
#pragma unroll
        for (int j = 0; j < 4; j++) {
            int idx = tid + j * 256;
            int r = idx >> 3, c = idx & 7;
            uint32_t doff = (uint32_t)(r * PITCH + c * 8) * 2;
            size_t goff = (size_t)r * CDIM + k0 + c * 8;
            cp_async16(s0 + doff,             Ab + goff);
            cp_async16(s0 + OFF_B * 2 + doff, Bb + goff);
        }
    };

    load_stage(0, 0);  CP_COMMIT();
    load_stage(1, 64); CP_COMMIT();

    const int NIT = CDIM / 64;   // 8
    for (int s = 0; s < NIT; s++) {
        CP_WAIT(1);
        __syncthreads();
        if (s + 2 < NIT) load_stage((s + 2) % 3, (s + 2) * 64);
        CP_COMMIT();

        const uint32_t pA = sb + (uint32_t)(s % 3) * SH * 2;
        const uint32_t pB = pA + OFF_B * 2;

#pragma unroll
        for (int kk = 0; kk < 64; kk += 16) {
            uint32_t ah[4][4], bh[4][2];
#pragma unroll
            for (int mi = 0; mi < 4; mi++) {
                uint32_t ro = (uint32_t)((wm + mi * 16 + aRow) * PITCH + kk + aK) * 2;
                ldm_x4(ah[mi], pA + ro);
            }
#pragma unroll
            for (int nb = 0; nb < 2; nb++) {
                uint32_t ro = (uint32_t)((wn + nb * 16 + bRowL) * PITCH + kk + bK) * 2;
                uint32_t th[4];
                ldm_x4(th, pB + ro);
                bh[nb * 2][0] = th[0];     bh[nb * 2][1] = th[1];
                bh[nb * 2 + 1][0] = th[2]; bh[nb * 2 + 1][1] = th[3];
            }
#pragma unroll
            for (int mi = 0; mi < 4; mi++)
#pragma unroll
                for (int ni = 0; ni < 4; ni++)
                    mma_f16(acc[mi][ni], ah[mi], bh[ni]);
        }
    }

    const int cr = L >> 2, cc = (L & 3) * 2;
#pragma unroll
    for (int mi = 0; mi < 4; mi++) {
#pragma unroll
        for (int ni = 0; ni < 4; ni++) {
            int row = m0 + wm + mi * 16 + cr;
            int col = n0 + wn + ni * 8 + cc;
            float b0 = 0.f, b1 = 0.f;
            if (bias) { b0 = bias[col]; b1 = bias[col + 1]; }
            if (HOUT) {
                __half* C = (__half*)Cv;
                *(__half2*)&C[(size_t)row * ldc + col] =
                    __floats2half2_rn(acc[mi][ni][0] + b0, acc[mi][ni][1] + b1);
                *(__half2*)&C[(size_t)(row + 8) * ldc + col] =
                    __floats2half2_rn(acc[mi][ni][2] + b0, acc[mi][ni][3] + b1);
            } else {
                float* C = (float*)Cv;
                *(float2*)&C[(size_t)row * ldc + col] =
                    make_float2(acc[mi][ni][0] + b0, acc[mi][ni][1] + b1);
                *(float2*)&C[(size_t)(row + 8) * ldc + col] =
                    make_float2(acc[mi][ni][2] + b0, acc[mi][ni][3] + b1);
            }
        }
    }
}

// ---------------------------------------------------------------------------
// fused fp32 -> fp16 converts
// ---------------------------------------------------------------------------
__global__ void cvt_all(const float4* __restrict__ x,
                        const float4* __restrict__ w0, const float4* __restrict__ w1,
                        const float4* __restrict__ w2, const float4* __restrict__ w3,
                        uint2* __restrict__ dx, uint2* __restrict__ dw)
{
    const int bx = blockIdx.x;
    union { uint2 u; __half b[4]; } H;
#define CVT4(V, DST, IDX) \
    H.b[0] = __float2half(V.x); H.b[1] = __float2half(V.y); \
    H.b[2] = __float2half(V.z); H.b[3] = __float2half(V.w); \
    DST[IDX] = H.u;
    if (bx < 2048) {
        const int i = bx * 256 + threadIdx.x;
        const int stride = 2048 * 256;
        float4 v0 = x[i];
        float4 v1 = x[i + stride];
        float4 v2 = x[i + 2 * stride];
        float4 v3 = x[i + 3 * stride];
        CVT4(v0, dx, i)
        CVT4(v1, dx, i + stride)
        CVT4(v2, dx, i + 2 * stride)
        CVT4(v3, dx, i + 3 * stride)
    } else {
        const int i = (bx - 2048) * 256 + threadIdx.x;
        float4 v0 = w0[i];
        float4 v1 = w1[i];
        float4 v2 = w2[i];
        float4 v3 = w3[i];
        CVT4(v0, dw, i)
        CVT4(v1, dw, 65536 + i)
        CVT4(v2, dw, 131072 + i)
        CVT4(v3, dw, 196608 + i)
    }
#undef CVT4
}

// ---------------------------------------------------------------------------
// Per-pixel attention (R16 body) + vhat tile:
// after Z, thread d builds vhat[d][h] = v[h][d] * 2/Z_d (fp16, 16B rows);
// output B-fragments come from 2x ldmatrix.x4.trans (vhat is row-major B).
// invb array and its per-thread LDS storm deleted. 32-bit store addressing.
// ---------------------------------------------------------------------------
#define PHQ 72

struct __align__(16) PixS {
    __half q16[8 * PHQ];
    __half k16[8 * PHQ];
    __half v16[8 * PHQ];
    float rn[16];                      // rn_q[0..7], rn_k*log2e[8..15]
    float sAraw[8][8];
    __align__(16) __half sAq[8][8];
    __align__(16) __half sAk[8][8];
    __align__(16) __half kT[64 * 8];   // k'[d][h] (log2-scaled), cross-warp
    __align__(16) __half vhat[64][8];  // v[h][d] * 2/Z_d
    __align__(16) float zpart[2][64];
};

__global__ __launch_bounds__(64) void attn_kernel(
    const __half* __restrict__ QKV, __half* __restrict__ scr)
{
    __shared__ PixS S;
    const int t6 = threadIdx.x;
    const int pix = blockIdx.x;
    const int w = t6 >> 5;
    const int L = t6 & 31;
    const int g4 = L >> 2, tq = L & 3;

    {
        const uint4* src = (const uint4*)(QKV + (size_t)pix * NQKV);
        const uint32_t off = (uint32_t)((t6 >> 3) * PHQ + (t6 & 7) * 8);
        *(uint4*)(S.q16 + off) = src[t6];
        *(uint4*)(S.k16 + off) = src[64 + t6];
        *(uint4*)(S.v16 + off) = src[128 + t6];
    }
    __syncthreads();

    if (w == 0) {
        // gram via mma: C(h,g) = sum_d v(h,d) v(g,d)
        float cg[4] = {0.f, 0.f, 0.f, 0.f};
        const uint32_t vb = smem_u32(S.v16);
        const int row = L & 7;
        const uint32_t abase = vb + (uint32_t)(row * PHQ) * 2;
        const uint32_t kA = (L >= 16) ? 16 : 0;
        const uint32_t kB = ((L >> 3) & 1) ? 16 : 0;
#pragma unroll
        for (int kj = 0; kj < 4; kj++) {
            uint32_t a[4], b[2];
            ldm_x4(a, abase + kA + (uint32_t)kj * 32);
            ldm_x2(b, abase + kB + (uint32_t)kj * 32);
            mma_f16(cg, a, b);
        }
        *(float2*)&S.sAraw[g4][2 * tq] = make_float2(cg[0], cg[1]);
    } else {
        // q/k norms (2 lanes per row)
        const int row = L >> 1, hf = L & 1;
        const __half* p = ((row < 8) ? S.q16 + row * PHQ
                                     : S.k16 + (row - 8) * PHQ) + hf * 32;
        float s = 0.f;
#pragma unroll
        for (int i = 0; i < 4; i++) {
            uint4 u = ((const uint4*)p)[i];
            const __half2* h2 = (const __half2*)&u;
#pragma unroll
            for (int j = 0; j < 4; j++) {
                float2 f = __half22float2(h2[j]);
                s = fmaf(f.x, f.x, fmaf(f.y, f.y, s));
            }
        }
        s += __shfl_xor_sync(0xffffffffu, s, 1);
        if (hf == 0) {
            float inv = 1.f / fmaxf(sqrtf(s), 1e-12f);
            S.rn[row] = (row < 8) ? inv : inv * LOG2E;
        }
    }
    __syncthreads();

    if (t6 < 8) {
        float rv[8];
#pragma unroll
        for (int g = 0; g < 8; g++)
            rv[g] = 1.f / fmaxf(sqrtf(S.sAraw[g][g]), 1e-12f);
        float rh = rv[t6], e[8], sum = 0.f;
#pragma unroll
        for (int g = 0; g < 8; g++) {
            e[g] = __expf(S.sAraw[t6][g] * rh * rv[g]);
            sum += e[g];
        }
        float inv = 1.f / sum;
        union { uint4 u; __half hh[8]; } Q_, K_;
#pragma unroll
        for (int g = 0; g < 8; g++) {
            float sft = e[g] * inv;
            Q_.hh[g] = __float2half(sft * S.rn[g]);
            K_.hh[g] = __float2half(sft * S.rn[8 + g]);
        }
        *(uint4*)&S.sAq[t6][0] = Q_.u;
        *(uint4*)&S.sAk[t6][0] = K_.u;
    }
    __syncthreads();

    // head-mix via mma; C-fragments reused as stage-2 fragments
    uint32_t qa[4], kb[8];
    {
        const int row = L & 7, grp = L >> 3;
        const uint32_t doff2 = (uint32_t)(w * 32 + grp * 8) * 2;
        uint32_t aq[4], ak[4], b2[2];
        ldm_x4_trans(aq, smem_u32(S.q16) + (uint32_t)(row * PHQ) * 2 + doff2);
        ldm_x4_trans(ak, smem_u32(S.k16) + (uint32_t)(row * PHQ) * 2 + doff2);
        uint32_t baddr = (L < 8) ? smem_u32(S.sAq) + (uint32_t)row * 16
                                 : smem_u32(S.sAk) + (uint32_t)(L & 7) * 16;
        ldm_x2(b2, baddr);
        float cq0[4] = {0,0,0,0}, cq1[4] = {0,0,0,0};
        float ck0[4] = {0,0,0,0}, ck1[4] = {0,0,0,0};
        mma_f16_k8(cq0, aq[0], aq[1], b2[0]);
        mma_f16_k8(cq1, aq[2], aq[3], b2[0]);
        mma_f16_k8(ck0, ak[0], ak[1], b2[1]);
        mma_f16_k8(ck1, ak[2], ak[3], b2[1]);
        qa[0] = pack_h2(cq0[0], cq0[1]);
        qa[1] = pack_h2(cq0[2], cq0[3]);
        qa[2] = pack_h2(cq1[0], cq1[1]);
        qa[3] = pack_h2(cq1[2], cq1[3]);
        uint32_t k0 = pack_h2(ck0[0], ck0[1]);
        uint32_t k1 = pack_h2(ck0[2], ck0[3]);
        uint32_t k2 = pack_h2(ck1[0], ck1[1]);
        uint32_t k3 = pack_h2(ck1[2], ck1[3]);
        kb[4 * w + 0] = k0; kb[4 * w + 1] = k1;
        kb[4 * w + 2] = k2; kb[4 * w + 3] = k3;
        const int dbase = w * 32 + g4;
        *(uint32_t*)&S.kT[(dbase)      * 8 + 2 * tq] = k0;
        *(uint32_t*)&S.kT[(dbase + 8)  * 8 + 2 * tq] = k1;
        *(uint32_t*)&S.kT[(dbase + 16) * 8 + 2 * tq] = k2;
        *(uint32_t*)&S.kT[(dbase + 24) * 8 + 2 * tq] = k3;
    }
    __syncthreads();
    ldm_x4(kb + 4 * (1 - w),
           smem_u32(S.kT) + (uint32_t)((1 - w) * 32 + L) * 16);

    // ================= stage-2 =================
    float Cs[2][8][4];
#pragma unroll
    for (int mi = 0; mi < 2; mi++)
#pragma unroll
        for (int nj = 0; nj < 8; nj++) {
            Cs[mi][nj][0] = Cs[mi][nj][1] = Cs[mi][nj][2] = Cs[mi][nj][3] = 0.f;
            mma_f16_k8(Cs[mi][nj], qa[2 * mi], qa[2 * mi + 1], kb[nj]);
        }

    uint32_t eh[2][8][2];
    float pzlo[8], pzhi[8];
#pragma unroll
    for (int nj = 0; nj < 8; nj++) { pzlo[nj] = 0.f; pzhi[nj] = 0.f; }
#pragma unroll
    for (int mi = 0; mi < 2; mi++)
#pragma unroll
        for (int nj = 0; nj < 8; nj++) {
            float e0 = ex2f(Cs[mi][nj][0]);
            float e1 = ex2f(Cs[mi][nj][1]);
            float e2 = ex2f(Cs[mi][nj][2]);
            float e3 = ex2f(Cs[mi][nj][3]);
            pzlo[nj] += e0 + e2;
            pzhi[nj] += e1 + e3;
            eh[mi][nj][0] = pack_h2(e0, e1);
            eh[mi][nj][1] = pack_h2(e2, e3);
        }
#pragma unroll
    for (int nj = 0; nj < 8; nj++) {
#pragma unroll
        for (int m = 4; m <= 16; m <<= 1) {
            pzlo[nj] += __shfl_xor_sync(0xffffffffu, pzlo[nj], m);
            pzhi[nj] += __shfl_xor_sync(0xffffffffu, pzhi[nj], m);
        }
    }
    if (g4 == 0) {
#pragma unroll
        for (int nj = 0; nj < 8; nj++)
            *(float2*)(S.zpart[w] + nj * 8 + 2 * tq) = make_float2(pzlo[nj], pzhi[nj]);
    }
    __syncthreads();

    // build vhat row d = t6: vhat[d][h] = v[h][d] * 2/Z_d
    {
        const int d = t6;
        float inv2 = 2.f / (S.zpart[0][d] + S.zpart[1][d]);
        union { uint4 u; __half hh[8]; } V_;
#pragma unroll
        for (int h = 0; h < 8; h++)
            V_.hh[h] = __float2half(__half2float(S.v16[h * PHQ + d]) * inv2);
        *(uint4*)&S.vhat[d][0] = V_.u;
    }
    __syncthreads();

    // output mma: B-fragments via ldmatrix.trans over vhat (row-major B)
    uint32_t bvf[8];
    ldm_x4_trans(bvf + 0, smem_u32(S.vhat) + (uint32_t)L * 16);
    ldm_x4_trans(bvf + 4, smem_u32(S.vhat) + (uint32_t)(32 + L) * 16);

    float Co[2][4];
    Co[0][0] = Co[0][1] = Co[0][2] = Co[0][3] = 0.f;
    Co[1][0] = Co[1][1] = Co[1][2] = Co[1][3] = 0.f;
#pragma unroll
    for (int kj = 0; kj < 4; kj++) {
        uint32_t bv[2] = { bvf[2 * kj], bvf[2 * kj + 1] };
#pragma unroll
        for (int mi = 0; mi < 2; mi++) {
            uint32_t av[4] = { eh[mi][2 * kj][0], eh[mi][2 * kj][1],
                               eh[mi][2 * kj + 1][0], eh[mi][2 * kj + 1][1] };
            mma_f16(Co[mi], av, bv);
        }
    }

    // store in scramble layout (32-bit offsets)
    {
        const int b = pix >> 12;
        const int n = pix & 4095;
        const uint32_t base =
            (uint32_t)(b * 4096 + (n >> 6)) * CDIM + (n & 63) * 8 + 2 * tq;
        const uint32_t estep = 64u * CDIM;
#pragma unroll
        for (int mi = 0; mi < 2; mi++) {
            uint32_t e = (uint32_t)(w * 32 + mi * 16 + g4);
            *(__half2*)(scr + base + e * estep) =
                __floats2half2_rn(Co[mi][0], Co[mi][1]);
            *(__half2*)(scr + base + (e + 8) * estep) =
                __floats2half2_rn(Co[mi][2], Co[mi][3]);
        }
    }
}

// ---------------------------------------------------------------------------
extern "C" void kernel_launch(void* const* d_in, const int* in_sizes, int n_in,
                              void* d_out, int out_size)
{
    const float* x     = (const float*)d_in[0];
    const float* Wq    = (const float*)d_in[1];
    const float* Wk    = (const float*)d_in[2];
    const float* Wv    = (const float*)d_in[3];
    // d_in[4] = conv_w: dead in the reference
    const float* projw = (const float*)d_in[5];
    const float* projb = (const float*)d_in[6];
    float* out = (float*)d_out;

    cudaFuncSetAttribute(gemm_f16<true>, cudaFuncAttributeMaxDynamicSharedMemorySize, GSMEM);
    cudaFuncSetAttribute(gemm_f16<false>, cudaFuncAttributeMaxDynamicSharedMemorySize, GSMEM);

    __half *x16, *s16, *w16, *qkv16;
    cudaGetSymbolAddress((void**)&x16, g_x16);
    cudaGetSymbolAddress((void**)&s16, g_s16);
    cudaGetSymbolAddress((void**)&w16, g_w16);
    cudaGetSymbolAddress((void**)&qkv16, g_qkv16);

    cvt_all<<<2304, 256>>>((const float4*)x,
                           (const float4*)Wq, (const float4*)Wk,
                           (const float4*)Wv, (const float4*)projw,
                           (uint2*)x16, (uint2*)w16);

    // fused QKV GEMM: [16384,512] x [1536,512]^T -> fp16 [16384,1536]
    gemm_f16<true><<<dim3(NQKV / 128, MTOT / 128), 256, GSMEM>>>(
        x16, w16, nullptr, qkv16, NQKV);

    attn_kernel<<<MTOT, 64>>>(qkv16, s16);

    // proj GEMM: [16384,512] x [512,512]^T -> fp32 out
    gemm_f16<false><<<dim3(CDIM / 128, MTOT / 128), 256, GSMEM>>>(
        s16, w16 + 3 * CDIM * CDIM, projb, out, CDIM);
}